// round 16
// baseline (speedup 1.0000x reference)
#include <cuda_runtime.h>
#include <cuda_bf16.h>
#include <math.h>
#include <stdint.h>

#define BB 4
#define SS 1024
#define DD 1024
#define HH 16
#define DQ 64
#define DV 32
#define BS (BB*SS)          // 4096
#define HDQ (HH*DQ)         // 1024
#define HDV (HH*DV)         // 512

typedef __nv_bfloat16 bf16;

// single dynamic-smem symbol for ALL kernels (typed locally)
extern __shared__ __align__(128) char dynsmem[];

// ---------------- scratch (device globals; allocation-free rule) ------------
__device__ bf16 g_xh[BS * DD],  g_xl[BS * DD];
__device__ bf16 g_WqkTh[2 * HDQ * DD], g_WqkTl[2 * HDQ * DD];  // [Wq^T;Wk^T]
__device__ bf16 g_WvTh[HDV * DD], g_WvTl[HDV * DD];
__device__ bf16 g_WoTh[DD * DD],  g_WoTl[DD * DD];
__device__ bf16 g_QKh[BS * 2 * HDQ], g_QKl[BS * 2 * HDQ];      // Q cols 0..1023, K cols 1024..2047
__device__ bf16 g_VTh[HDV * BS], g_VTl[HDV * BS];
__device__ bf16 g_Ch[BS * DD],   g_Cl[BS * DD];
__device__ float g_S[(size_t)BB * HH * SS * SS];

// ---------------- generic helpers -------------------------------------------
__device__ __forceinline__ void split_bf(float f, bf16& h, bf16& l) {
    h = __float2bfloat16(f);
    l = __float2bfloat16(f - __bfloat162float(h));
}
__device__ __forceinline__ uint32_t pk2(bf16 a, bf16 b) {
    return (uint32_t)__bfloat16_as_ushort(a) |
           ((uint32_t)__bfloat16_as_ushort(b) << 16);
}
__device__ __forceinline__ void mma16(float* c, const uint32_t* a, const uint32_t* b) {
    asm("mma.sync.aligned.m16n8k16.row.col.f32.bf16.bf16.f32 "
        "{%0,%1,%2,%3}, {%4,%5,%6,%7}, {%8,%9}, {%0,%1,%2,%3};"
        : "+f"(c[0]), "+f"(c[1]), "+f"(c[2]), "+f"(c[3])
        : "r"(a[0]), "r"(a[1]), "r"(a[2]), "r"(a[3]), "r"(b[0]), "r"(b[1]));
}
__device__ __forceinline__ void ldsm4(uint32_t a, uint32_t& r0, uint32_t& r1,
                                      uint32_t& r2, uint32_t& r3) {
    asm volatile("ldmatrix.sync.aligned.m8n8.x4.shared.b16 {%0,%1,%2,%3}, [%4];"
        : "=r"(r0), "=r"(r1), "=r"(r2), "=r"(r3) : "r"(a));
}
__device__ __forceinline__ void cpa16(uint32_t s, const void* g) {
    asm volatile("cp.async.cg.shared.global [%0], [%1], 16;" :: "r"(s), "l"(g));
}
__device__ __forceinline__ void cp_commit() { asm volatile("cp.async.commit_group;"); }
__device__ __forceinline__ void cp_wait1()  { asm volatile("cp.async.wait_group 1;"); }
__device__ __forceinline__ void cp_wait0()  { asm volatile("cp.async.wait_group 0;"); }
__device__ __forceinline__ uint32_t s2u(const void* p) {
    uint32_t a;
    asm("{ .reg .u64 t; cvta.to.shared.u64 t, %1; cvt.u32.u64 %0, t; }"
        : "=r"(a) : "l"(p));
    return a;
}
__device__ __forceinline__ void stg_cs_f2(float* p, float2 v) {
    asm volatile("st.global.cs.v2.f32 [%0], {%1, %2};" :: "l"(p), "f"(v.x), "f"(v.y));
}
__device__ __forceinline__ void stg_cs_f4(float* p, float4 v) {
    asm volatile("st.global.cs.v4.f32 [%0], {%1, %2, %3, %4};"
                 :: "l"(p), "f"(v.x), "f"(v.y), "f"(v.z), "f"(v.w));
}

// ---------------- split pre-passes ------------------------------------------
__global__ __launch_bounds__(256) void split_x_kernel(
    const float* __restrict__ in, bf16* __restrict__ hi,
    bf16* __restrict__ lo, int n4)
{
    for (int i = blockIdx.x * 256 + threadIdx.x; i < n4; i += gridDim.x * 256) {
        float4 v = ((const float4*)in)[i];
        bf16 h0, l0, h1, l1, h2, l2, h3, l3;
        split_bf(v.x, h0, l0); split_bf(v.y, h1, l1);
        split_bf(v.z, h2, l2); split_bf(v.w, h3, l3);
        ((uint2*)hi)[i] = make_uint2(pk2(h0, h1), pk2(h2, h3));
        ((uint2*)lo)[i] = make_uint2(pk2(l0, l1), pk2(l2, l3));
    }
}

// Transpose+split all 4 weight matrices in ONE launch (grid.z selects W).
struct SplitArgs {
    const float* W[4];
    bf16* Th[4];
    bf16* Tl[4];
    int N[4];
};
__global__ void splitT_all(SplitArgs a)
{
    __shared__ float t[32][33];
    const int w = blockIdx.z;
    const int N = a.N[w];
    const int n0 = blockIdx.x * 32, k0 = blockIdx.y * 32;
    if (n0 >= N) return;
    const float* W = a.W[w];
    bf16* Th = a.Th[w];
    bf16* Tl = a.Tl[w];
    const int K = DD;
    const int tx = threadIdx.x, ty = threadIdx.y;
#pragma unroll
    for (int i = 0; i < 32; i += 8)
        t[ty + i][tx] = W[(size_t)(k0 + ty + i) * N + n0 + tx];
    __syncthreads();
#pragma unroll
    for (int i = 0; i < 32; i += 8) {
        float v = t[tx][ty + i];
        bf16 h, l; split_bf(v, h, l);
        Th[(size_t)(n0 + ty + i) * K + k0 + tx] = h;
        Tl[(size_t)(n0 + ty + i) * K + k0 + tx] = l;
    }
}

// ---------------- unified bf16-split GEMM (cp.async + ldmatrix) -------------
// C[M,N] = (A @ Bt^T) * scale + bias   (A row-major [M][K], Bt row-major [N][K])
// OUT=0: fp32 C (streaming stores). OUT=1: split bf16 row-major (dual bias
// via biasB at col >= nsplit). OUT=2: split bf16 transposed.
#define PITCH 40             // bf16 per smem row (32 data + 8 pad)
#define TSZ (128 * PITCH)    // one plane-buffer, bf16 elements
#define GEMM_SMEM (8 * TSZ * 2)   // 81920 B

__device__ __forceinline__ int slot_off(int plane, int buf) {
    return (plane * 2 + buf) * TSZ;
}

template<int OUT>
__global__ __launch_bounds__(256, 2) void gemm_bf16(
    const bf16* __restrict__ Ah, const bf16* __restrict__ Al, int lda,
    const bf16* __restrict__ Bth, const bf16* __restrict__ Btl, int ldb,
    const float* __restrict__ bias, const float* __restrict__ biasB, int nsplit,
    float scale,
    float* __restrict__ outF, bf16* __restrict__ outH, bf16* __restrict__ outL,
    int ldc, int M, int N, int K, size_t zb, size_t zh, size_t cB)
{
    bf16* smem = (bf16*)dynsmem;
    const int z = blockIdx.z;
    const size_t offAB = (size_t)(z >> 4) * zb + (size_t)(z & 15) * zh;

    const int m0 = blockIdx.y * 128, n0 = blockIdx.x * 128;
    const int tid = threadIdx.x, lane = tid & 31, wid = tid >> 5;
    const int wm0 = (wid >> 2) * 64, wn0 = (wid & 3) * 32;
    const int lr = lane >> 2, lc = lane & 3;

    const int rowA = lane & 15;
    const int kA = (lane >> 4) * 8;
    const int rowB = (lane & 7) + ((lane >> 4) * 8);
    const int kB = ((lane >> 3) & 1) * 8;

    const uint32_t sbase = s2u(smem);

    float acc[4][4][4];
#pragma unroll
    for (int i = 0; i < 4; i++)
#pragma unroll
        for (int j = 0; j < 4; j++)
#pragma unroll
            for (int k = 0; k < 4; k++) acc[i][j][k] = 0.0f;

    const int nk = K / 32;

    auto loadAB = [&](int buf, int k0) {
#pragma unroll
        for (int j = 0; j < 2; j++) {
            int idx = tid + j * 256;
            int r = idx >> 2, cc = idx & 3;
            int rp = r * PITCH + cc * 8;
            size_t gA = offAB + (size_t)(m0 + r) * lda + k0 + cc * 8;
            size_t gB = offAB + (size_t)(n0 + r) * ldb + k0 + cc * 8;
            cpa16(sbase + (slot_off(0, buf) + rp) * 2, Ah + gA);
            cpa16(sbase + (slot_off(1, buf) + rp) * 2, Al + gA);
            cpa16(sbase + (slot_off(2, buf) + rp) * 2, Bth + gB);
            cpa16(sbase + (slot_off(3, buf) + rp) * 2, Btl + gB);
        }
    };

    loadAB(0, 0);
    cp_commit();

    for (int kt = 0; kt < nk; kt++) {
        const int buf = kt & 1;
        if (kt + 1 < nk) {
            loadAB(buf ^ 1, (kt + 1) * 32);
            cp_commit();
            cp_wait1();
        } else {
            cp_wait0();
        }
        __syncthreads();

#pragma unroll
        for (int ks = 0; ks < 32; ks += 16) {
            uint32_t ah[4][4], al[4][4];
#pragma unroll
            for (int mt = 0; mt < 4; mt++) {
                uint32_t aoff = ((wm0 + mt * 16 + rowA) * PITCH + ks + kA) * 2;
                ldsm4(sbase + slot_off(0, buf) * 2 + aoff,
                      ah[mt][0], ah[mt][1], ah[mt][2], ah[mt][3]);
                ldsm4(sbase + slot_off(1, buf) * 2 + aoff,
                      al[mt][0], al[mt][1], al[mt][2], al[mt][3]);
            }
            uint32_t bhq[2][4], blq[2][4];
#pragma unroll
            for (int np = 0; np < 2; np++) {
                uint32_t boff = ((wn0 + np * 16 + rowB) * PITCH + ks + kB) * 2;
                ldsm4(sbase + slot_off(2, buf) * 2 + boff,
                      bhq[np][0], bhq[np][1], bhq[np][2], bhq[np][3]);
                ldsm4(sbase + slot_off(3, buf) * 2 + boff,
                      blq[np][0], blq[np][1], blq[np][2], blq[np][3]);
            }
#pragma unroll
            for (int nt = 0; nt < 4; nt++) {
                uint32_t bh[2] = {bhq[nt >> 1][(nt & 1) * 2],
                                  bhq[nt >> 1][(nt & 1) * 2 + 1]};
                uint32_t bl[2] = {blq[nt >> 1][(nt & 1) * 2],
                                  blq[nt >> 1][(nt & 1) * 2 + 1]};
#pragma unroll
                for (int mt = 0; mt < 4; mt++) {
                    mma16(acc[mt][nt], ah[mt], bh);
                    mma16(acc[mt][nt], ah[mt], bl);
                    mma16(acc[mt][nt], al[mt], bh);
                }
            }
        }
        __syncthreads();
    }

    // epilogue
#pragma unroll
    for (int mt = 0; mt < 4; mt++)
#pragma unroll
        for (int nt = 0; nt < 4; nt++) {
            int r = m0 + wm0 + mt * 16 + lr;
            int c = n0 + wn0 + nt * 8 + 2 * lc;
            float b0 = 0.0f, b1 = 0.0f;
            if (bias) {
                const float* bp = (c >= nsplit) ? (biasB - nsplit) : bias;
                b0 = bp[c]; b1 = bp[c + 1];
            }
            float v00 = acc[mt][nt][0] * scale + b0;
            float v01 = acc[mt][nt][1] * scale + b1;
            float v10 = acc[mt][nt][2] * scale + b0;
            float v11 = acc[mt][nt][3] * scale + b1;
            if (OUT == 0) {
                float* C = outF + (size_t)z * cB;
                stg_cs_f2(C + (size_t)r * ldc + c, make_float2(v00, v01));
                stg_cs_f2(C + (size_t)(r + 8) * ldc + c, make_float2(v10, v11));
            } else if (OUT == 1) {
                bf16 h0, l0, h1, l1;
                split_bf(v00, h0, l0); split_bf(v01, h1, l1);
                *(uint32_t*)(outH + (size_t)r * ldc + c) = pk2(h0, h1);
                *(uint32_t*)(outL + (size_t)r * ldc + c) = pk2(l0, l1);
                split_bf(v10, h0, l0); split_bf(v11, h1, l1);
                *(uint32_t*)(outH + (size_t)(r + 8) * ldc + c) = pk2(h0, h1);
                *(uint32_t*)(outL + (size_t)(r + 8) * ldc + c) = pk2(l0, l1);
            } else {
                bf16 h, l;
                split_bf(v00, h, l);
                outH[(size_t)c * ldc + r] = h; outL[(size_t)c * ldc + r] = l;
                split_bf(v01, h, l);
                outH[(size_t)(c + 1) * ldc + r] = h; outL[(size_t)(c + 1) * ldc + r] = l;
                split_bf(v10, h, l);
                outH[(size_t)c * ldc + r + 8] = h; outL[(size_t)c * ldc + r + 8] = l;
                split_bf(v11, h, l);
                outH[(size_t)(c + 1) * ldc + r + 8] = h; outL[(size_t)(c + 1) * ldc + r + 8] = l;
            }
        }
}

// ---------------- softmax: probs -> attn (d_out), float4 I/O, .cs stores ----
#define SMROW 1032
#define SOFT_SMEM (16 * SMROW * 4)
__global__ __launch_bounds__(256) void softmax_kernel(
    const float* __restrict__ Sc, float* __restrict__ attn)
{
    float* ssc = (float*)dynsmem;
    __shared__ float mF[16], iF[16], mB[16], iB[16];

    const int bh = blockIdx.y;
    const int q0 = blockIdx.x * 16;
    const int tid = threadIdx.x;

    const float4* src4 = (const float4*)(Sc + (size_t)bh * SS * SS + (size_t)q0 * SS);
    for (int i = tid; i < 16 * 256; i += 256) {
        int r = i >> 8, c = i & 255;
        *(float4*)(ssc + r * SMROW + c * 4) = src4[r * 256 + c];
    }
    __syncthreads();

    const int r = tid >> 4;
    const int t = tid & 15;
    const int q = q0 + r;
    const float* row = ssc + r * SMROW;

    float mf = -1e30f, mb = -1e30f;
#pragma unroll 8
    for (int i = 0; i < 64; i++) {
        int k = t + (i << 4);
        float v = row[k];
        if (k <= q) mf = fmaxf(mf, v);
        if (k >= q) mb = fmaxf(mb, v);
    }
#pragma unroll
    for (int o = 8; o > 0; o >>= 1) {
        mf = fmaxf(mf, __shfl_xor_sync(0xffffffffu, mf, o));
        mb = fmaxf(mb, __shfl_xor_sync(0xffffffffu, mb, o));
    }
    float sf = 0.0f, sb2 = 0.0f;
#pragma unroll 8
    for (int i = 0; i < 64; i++) {
        int k = t + (i << 4);
        float v = row[k];
        if (k <= q) sf += __expf(v - mf);
        if (k >= q) sb2 += __expf(v - mb);
    }
#pragma unroll
    for (int o = 8; o > 0; o >>= 1) {
        sf += __shfl_xor_sync(0xffffffffu, sf, o);
        sb2 += __shfl_xor_sync(0xffffffffu, sb2, o);
    }
    if (t == 0) {
        mF[r] = mf; iF[r] = 1.0f / sf;
        mB[r] = mb; iB[r] = 1.0f / sb2;
    }
    __syncthreads();

    float* dst = attn + (size_t)bh * SS * 2 * SS + (size_t)q0 * 2048;
    for (int i = tid; i < 16 * 256; i += 256) {
        int rr = i >> 8, c = (i & 255) * 4;
        int qq = q0 + rr;
        float4 v = *(const float4*)(ssc + rr * SMROW + c);
        float mf2 = mF[rr], if2 = iF[rr], mb2 = mB[rr], ib2 = iB[rr];
        float4 pf, pb;
        pf.x = (c + 0 <= qq) ? __expf(v.x - mf2) * if2 : 0.0f;
        pf.y = (c + 1 <= qq) ? __expf(v.y - mf2) * if2 : 0.0f;
        pf.z = (c + 2 <= qq) ? __expf(v.z - mf2) * if2 : 0.0f;
        pf.w = (c + 3 <= qq) ? __expf(v.w - mf2) * if2 : 0.0f;
        pb.x = (c + 0 >= qq) ? __expf(v.x - mb2) * ib2 : 0.0f;
        pb.y = (c + 1 >= qq) ? __expf(v.y - mb2) * ib2 : 0.0f;
        pb.z = (c + 2 >= qq) ? __expf(v.z - mb2) * ib2 : 0.0f;
        pb.w = (c + 3 >= qq) ? __expf(v.w - mb2) * ib2 : 0.0f;
        stg_cs_f4(dst + (size_t)rr * 2048 + c, pf);
        stg_cs_f4(dst + (size_t)rr * 2048 + 1024 + c, pb);
    }
}

// ---------------- PV: ctx = P @ V  (ldmatrix + cp.async) --------------------
#define VSZ (32 * PITCH)
#define PV_SMEM ((4 * TSZ + 4 * VSZ) * 2)   // 51200 B

__global__ __launch_bounds__(256, 2) void pv_bf16(const float* __restrict__ attn)
{
    bf16* smem = (bf16*)dynsmem;

    const int bh = blockIdx.z;
    const int dir = blockIdx.y;
    const int q0 = blockIdx.x * 128;
    const int b = bh >> 4, h = bh & 15;
    const int tid = threadIdx.x, lane = tid & 31, wid = tid >> 5;
    const int lr = lane >> 2, lc = lane & 3;

    const int rowA = lane & 15;
    const int kA = (lane >> 4) * 8;
    const int rowB = (lane & 7) + ((lane >> 4) * 8);
    const int kB = ((lane >> 3) & 1) * 8;

    const float* Pb = attn + (size_t)bh * SS * 2 * SS + (size_t)dir * SS;
    const bf16* Vth = g_VTh + (size_t)h * 32 * BS + (size_t)b * SS;
    const bf16* Vtl = g_VTl + (size_t)h * 32 * BS + (size_t)b * SS;

    const uint32_t sbase = s2u(smem);

    float acc[4][4];
#pragma unroll
    for (int i = 0; i < 4; i++)
#pragma unroll
        for (int j = 0; j < 4; j++) acc[i][j] = 0.0f;

    auto loadP = [&](int buf, int k0) {
#pragma unroll
        for (int j = 0; j < 2; j++) {
            int idx = tid + j * 256;
            int r = idx >> 2, cc = idx & 3;
            const float* src = Pb + (size_t)(q0 + r) * 2048 + k0 + cc * 8;
            float4 p0 = *(const float4*)(src);
            float4 p1 = *(const float4*)(src + 4);
            bf16 h0, l0, h1, l1, h2, l2, h3, l3, h4, l4, h5, l5, h6, l6, h7, l7;
            split_bf(p0.x, h0, l0); split_bf(p0.y, h1, l1);
            split_bf(p0.z, h2, l2); split_bf(p0.w, h3, l3);
            split_bf(p1.x, h4, l4); split_bf(p1.y, h5, l5);
            split_bf(p1.z, h6, l6); split_bf(p1.w, h7, l7);
            uint4 hv = make_uint4(pk2(h0, h1), pk2(h2, h3), pk2(h4, h5), pk2(h6, h7));
            uint4 lv = make_uint4(pk2(l0, l1), pk2(l2, l3), pk2(l4, l5), pk2(l6, l7));
            *(uint4*)(smem + (0 * 2 + buf) * TSZ + r * PITCH + cc * 8) = hv;
            *(uint4*)(smem + (1 * 2 + buf) * TSZ + r * PITCH + cc * 8) = lv;
        }
    };
    auto loadV = [&](int buf, int k0) {
        int half = tid >> 7;
        int d = (tid >> 2) & 31;
        int cc = tid & 3;
        const bf16* src = (half == 0 ? Vth : Vtl);
        uint32_t s = sbase + (4 * TSZ + (half * 2 + buf) * VSZ
                              + d * PITCH + cc * 8) * 2;
        cpa16(s, src + (size_t)d * BS + k0 + cc * 8);
    };

    loadV(0, 0);
    cp_commit();
    loadP(0, 0);

    const int nk = SS / 32;
    for (int kt = 0; kt < nk; kt++) {
        const int buf = kt & 1;
        if (kt + 1 < nk) {
            loadV(buf ^ 1, (kt + 1) * 32);
            cp_commit();
            cp_wait1();
        } else {
            cp_wait0();
        }
        __syncthreads();
        if (kt + 1 < nk) loadP(buf ^ 1, (kt + 1) * 32);

#pragma unroll
        for (int ks = 0; ks < 32; ks += 16) {
            uint32_t aoff = ((wid * 16 + rowA) * PITCH + ks + kA) * 2;
            uint32_t ah[4], al[4];
            ldsm4(sbase + ((0 * 2 + buf) * TSZ) * 2 + aoff, ah[0], ah[1], ah[2], ah[3]);
            ldsm4(sbase + ((1 * 2 + buf) * TSZ) * 2 + aoff, al[0], al[1], al[2], al[3]);
            uint32_t bhq[2][4], blq[2][4];
#pragma unroll
            for (int np = 0; np < 2; np++) {
                uint32_t boff = ((np * 16 + rowB) * PITCH + ks + kB) * 2;
                ldsm4(sbase + (4 * TSZ + (0 * 2 + buf) * VSZ) * 2 + boff,
                      bhq[np][0], bhq[np][1], bhq[np][2], bhq[np][3]);
                ldsm4(sbase + (4 * TSZ + (1 * 2 + buf) * VSZ) * 2 + boff,
                      blq[np][0], blq[np][1], blq[np][2], blq[np][3]);
            }
#pragma unroll
            for (int nt = 0; nt < 4; nt++) {
                uint32_t bh[2] = {bhq[nt >> 1][(nt & 1) * 2],
                                  bhq[nt >> 1][(nt & 1) * 2 + 1]};
                uint32_t bl[2] = {blq[nt >> 1][(nt & 1) * 2],
                                  blq[nt >> 1][(nt & 1) * 2 + 1]};
                mma16(acc[nt], ah, bh);
                mma16(acc[nt], ah, bl);
                mma16(acc[nt], al, bh);
            }
        }
        __syncthreads();
    }

#pragma unroll
    for (int nt = 0; nt < 4; nt++) {
        int r = q0 + wid * 16 + lr;
        int c = dir * HDV + h * DV + nt * 8 + 2 * lc;
        bf16 h0, l0, h1, l1;
        split_bf(acc[nt][0], h0, l0); split_bf(acc[nt][1], h1, l1);
        *(uint32_t*)(g_Ch + (size_t)((size_t)b * SS + r) * DD + c) = pk2(h0, h1);
        *(uint32_t*)(g_Cl + (size_t)((size_t)b * SS + r) * DD + c) = pk2(l0, l1);
        split_bf(acc[nt][2], h0, l0); split_bf(acc[nt][3], h1, l1);
        *(uint32_t*)(g_Ch + (size_t)((size_t)b * SS + r + 8) * DD + c) = pk2(h0, h1);
        *(uint32_t*)(g_Cl + (size_t)((size_t)b * SS + r + 8) * DD + c) = pk2(l0, l1);
    }
}

// ---------------- launch -----------------------------------------------------
extern "C" void kernel_launch(void* const* d_in, const int* in_sizes, int n_in,
                              void* d_out, int out_size)
{
    const float* x  = (const float*)d_in[0];
    const float* Wq = (const float*)d_in[1];
    const float* bq = (const float*)d_in[2];
    const float* Wk = (const float*)d_in[3];
    const float* bk = (const float*)d_in[4];
    const float* Wv = (const float*)d_in[5];
    const float* bv = (const float*)d_in[6];
    const float* Wo = (const float*)d_in[7];
    const float* bo = (const float*)d_in[8];

    float* out  = (float*)d_out;
    float* attn = out + (size_t)BS * DD;

    bf16 *xh, *xl, *WqkTh, *WqkTl, *WvTh, *WvTl, *WoTh, *WoTl;
    bf16 *QKh, *QKl, *VTh, *VTl, *Ch, *Cl;
    float* pS;
    cudaGetSymbolAddress((void**)&xh, g_xh);       cudaGetSymbolAddress((void**)&xl, g_xl);
    cudaGetSymbolAddress((void**)&WqkTh, g_WqkTh); cudaGetSymbolAddress((void**)&WqkTl, g_WqkTl);
    cudaGetSymbolAddress((void**)&WvTh, g_WvTh);   cudaGetSymbolAddress((void**)&WvTl, g_WvTl);
    cudaGetSymbolAddress((void**)&WoTh, g_WoTh);   cudaGetSymbolAddress((void**)&WoTl, g_WoTl);
    cudaGetSymbolAddress((void**)&QKh, g_QKh);     cudaGetSymbolAddress((void**)&QKl, g_QKl);
    cudaGetSymbolAddress((void**)&VTh, g_VTh);     cudaGetSymbolAddress((void**)&VTl, g_VTl);
    cudaGetSymbolAddress((void**)&Ch, g_Ch);       cudaGetSymbolAddress((void**)&Cl, g_Cl);
    cudaGetSymbolAddress((void**)&pS, g_S);

    cudaFuncSetAttribute(gemm_bf16<0>, cudaFuncAttributeMaxDynamicSharedMemorySize, GEMM_SMEM);
    cudaFuncSetAttribute(gemm_bf16<1>, cudaFuncAttributeMaxDynamicSharedMemorySize, GEMM_SMEM);
    cudaFuncSetAttribute(gemm_bf16<2>, cudaFuncAttributeMaxDynamicSharedMemorySize, GEMM_SMEM);
    cudaFuncSetAttribute(pv_bf16, cudaFuncAttributeMaxDynamicSharedMemorySize, PV_SMEM);
    cudaFuncSetAttribute(softmax_kernel,
                         cudaFuncAttributeMaxDynamicSharedMemorySize, SOFT_SMEM);

    // split passes (2 launches)
    split_x_kernel<<<512, 256>>>(x, xh, xl, BS * DD / 4);
    SplitArgs sa;
    sa.W[0] = Wq; sa.Th[0] = WqkTh;                    sa.Tl[0] = WqkTl;                    sa.N[0] = HDQ;
    sa.W[1] = Wk; sa.Th[1] = WqkTh + (size_t)HDQ * DD; sa.Tl[1] = WqkTl + (size_t)HDQ * DD; sa.N[1] = HDQ;
    sa.W[2] = Wv; sa.Th[2] = WvTh;                     sa.Tl[2] = WvTl;                     sa.N[2] = HDV;
    sa.W[3] = Wo; sa.Th[3] = WoTh;                     sa.Tl[3] = WoTl;                     sa.N[3] = DD;
    splitT_all<<<dim3(32, 32, 4), dim3(32, 8)>>>(sa);

    // merged QK projection: one launch, N=2048, bias bq for c<1024, bk after
    gemm_bf16<1><<<dim3(16, 32, 1), 256, GEMM_SMEM>>>(
        xh, xl, DD, WqkTh, WqkTl, DD, bq, bk, HDQ, 1.0f,
        nullptr, QKh, QKl, 2 * HDQ, BS, 2 * HDQ, DD, 0, 0, 0);
    gemm_bf16<2><<<dim3(4, 32, 1), 256, GEMM_SMEM>>>(
        xh, xl, DD, WvTh, WvTl, DD, bv, bv, HDV, 1.0f,
        nullptr, VTh, VTl, BS, BS, HDV, DD, 0, 0, 0);

    // scores: per (b,h) Q @ K^T * 0.125 (Q at col 0, K at col 1024 of QK)
    gemm_bf16<0><<<dim3(8, 8, BB * HH), 256, GEMM_SMEM>>>(
        QKh, QKl, 2 * HDQ, QKh + HDQ, QKl + HDQ, 2 * HDQ, nullptr, nullptr, SS, 0.125f,
        pS, nullptr, nullptr, SS, SS, SS, DQ,
        (size_t)SS * 2 * HDQ, (size_t)DQ, (size_t)SS * SS);

    // softmax + prob write (float4 I/O, streaming stores)
    softmax_kernel<<<dim3(SS / 16, BB * HH), 256, SOFT_SMEM>>>(pS, attn);

    // PV
    pv_bf16<<<dim3(SS / 128, 2, BB * HH), 256, PV_SMEM>>>(attn);

    // output projection
    gemm_bf16<0><<<dim3(8, 32, 1), 256, GEMM_SMEM>>>(
        Ch, Cl, DD, WoTh, WoTl, DD, bo, bo, DD, 1.0f,
        out, nullptr, nullptr, DD, BS, DD, DD, 0, 0, 0);
}

// round 17
// speedup vs baseline: 1.0178x; 1.0178x over previous
#include <cuda_runtime.h>
#include <cuda_bf16.h>
#include <math.h>
#include <stdint.h>

#define BB 4
#define SS 1024
#define DD 1024
#define HH 16
#define DQ 64
#define DV 32
#define BS (BB*SS)          // 4096
#define HDQ (HH*DQ)         // 1024
#define HDV (HH*DV)         // 512

typedef __nv_bfloat16 bf16;

// single dynamic-smem symbol for ALL kernels (typed locally)
extern __shared__ __align__(128) char dynsmem[];

// ---------------- scratch (device globals; allocation-free rule) ------------
__device__ bf16 g_xh[BS * DD],  g_xl[BS * DD];
__device__ bf16 g_WqkTh[2 * HDQ * DD], g_WqkTl[2 * HDQ * DD];  // [Wq^T;Wk^T]
__device__ bf16 g_WvTh[HDV * DD], g_WvTl[HDV * DD];
__device__ bf16 g_WoTh[DD * DD],  g_WoTl[DD * DD];
__device__ bf16 g_QKh[BS * 2 * HDQ], g_QKl[BS * 2 * HDQ];      // Q cols 0..1023, K cols 1024..2047
__device__ bf16 g_VTh[HDV * BS], g_VTl[HDV * BS];
__device__ bf16 g_Ch[BS * DD],   g_Cl[BS * DD];
__device__ float g_S[(size_t)BB * HH * SS * SS];

// ---------------- generic helpers -------------------------------------------
__device__ __forceinline__ void split_bf(float f, bf16& h, bf16& l) {
    h = __float2bfloat16(f);
    l = __float2bfloat16(f - __bfloat162float(h));
}
__device__ __forceinline__ uint32_t pk2(bf16 a, bf16 b) {
    return (uint32_t)__bfloat16_as_ushort(a) |
           ((uint32_t)__bfloat16_as_ushort(b) << 16);
}
__device__ __forceinline__ void mma16(float* c, const uint32_t* a, const uint32_t* b) {
    asm("mma.sync.aligned.m16n8k16.row.col.f32.bf16.bf16.f32 "
        "{%0,%1,%2,%3}, {%4,%5,%6,%7}, {%8,%9}, {%0,%1,%2,%3};"
        : "+f"(c[0]), "+f"(c[1]), "+f"(c[2]), "+f"(c[3])
        : "r"(a[0]), "r"(a[1]), "r"(a[2]), "r"(a[3]), "r"(b[0]), "r"(b[1]));
}
__device__ __forceinline__ void ldsm4(uint32_t a, uint32_t& r0, uint32_t& r1,
                                      uint32_t& r2, uint32_t& r3) {
    asm volatile("ldmatrix.sync.aligned.m8n8.x4.shared.b16 {%0,%1,%2,%3}, [%4];"
        : "=r"(r0), "=r"(r1), "=r"(r2), "=r"(r3) : "r"(a));
}
__device__ __forceinline__ void cpa16(uint32_t s, const void* g) {
    asm volatile("cp.async.cg.shared.global [%0], [%1], 16;" :: "r"(s), "l"(g));
}
__device__ __forceinline__ void cp_commit() { asm volatile("cp.async.commit_group;"); }
__device__ __forceinline__ void cp_wait1()  { asm volatile("cp.async.wait_group 1;"); }
__device__ __forceinline__ void cp_wait0()  { asm volatile("cp.async.wait_group 0;"); }
__device__ __forceinline__ uint32_t s2u(const void* p) {
    uint32_t a;
    asm("{ .reg .u64 t; cvta.to.shared.u64 t, %1; cvt.u32.u64 %0, t; }"
        : "=r"(a) : "l"(p));
    return a;
}

// ---------------- split pre-passes ------------------------------------------
__global__ __launch_bounds__(256) void split_x_kernel(
    const float* __restrict__ in, bf16* __restrict__ hi,
    bf16* __restrict__ lo, int n4)
{
    for (int i = blockIdx.x * 256 + threadIdx.x; i < n4; i += gridDim.x * 256) {
        float4 v = ((const float4*)in)[i];
        bf16 h0, l0, h1, l1, h2, l2, h3, l3;
        split_bf(v.x, h0, l0); split_bf(v.y, h1, l1);
        split_bf(v.z, h2, l2); split_bf(v.w, h3, l3);
        ((uint2*)hi)[i] = make_uint2(pk2(h0, h1), pk2(h2, h3));
        ((uint2*)lo)[i] = make_uint2(pk2(l0, l1), pk2(l2, l3));
    }
}

// Transpose+split all 4 weight matrices in ONE launch (grid.z selects W).
struct SplitArgs {
    const float* W[4];
    bf16* Th[4];
    bf16* Tl[4];
    int N[4];
};
__global__ void splitT_all(SplitArgs a)
{
    __shared__ float t[32][33];
    const int w = blockIdx.z;
    const int N = a.N[w];
    const int n0 = blockIdx.x * 32, k0 = blockIdx.y * 32;
    if (n0 >= N) return;
    const float* W = a.W[w];
    bf16* Th = a.Th[w];
    bf16* Tl = a.Tl[w];
    const int K = DD;
    const int tx = threadIdx.x, ty = threadIdx.y;
#pragma unroll
    for (int i = 0; i < 32; i += 8)
        t[ty + i][tx] = W[(size_t)(k0 + ty + i) * N + n0 + tx];
    __syncthreads();
#pragma unroll
    for (int i = 0; i < 32; i += 8) {
        float v = t[tx][ty + i];
        bf16 h, l; split_bf(v, h, l);
        Th[(size_t)(n0 + ty + i) * K + k0 + tx] = h;
        Tl[(size_t)(n0 + ty + i) * K + k0 + tx] = l;
    }
}

// ---------------- unified bf16-split GEMM (cp.async + ldmatrix) -------------
// C[M,N] = (A @ Bt^T) * scale + bias   (A row-major [M][K], Bt row-major [N][K])
// OUT=0: fp32 C. OUT=1: split bf16 row-major (dual bias via biasB at
// col >= nsplit). OUT=2: split bf16 transposed.
#define PITCH 40             // bf16 per smem row (32 data + 8 pad)
#define TSZ (128 * PITCH)    // one plane-buffer, bf16 elements
#define GEMM_SMEM (8 * TSZ * 2)   // 81920 B

__device__ __forceinline__ int slot_off(int plane, int buf) {
    return (plane * 2 + buf) * TSZ;
}

template<int OUT>
__global__ __launch_bounds__(256, 2) void gemm_bf16(
    const bf16* __restrict__ Ah, const bf16* __restrict__ Al, int lda,
    const bf16* __restrict__ Bth, const bf16* __restrict__ Btl, int ldb,
    const float* __restrict__ bias, const float* __restrict__ biasB, int nsplit,
    float scale,
    float* __restrict__ outF, bf16* __restrict__ outH, bf16* __restrict__ outL,
    int ldc, int M, int N, int K, size_t zb, size_t zh, size_t cB)
{
    bf16* smem = (bf16*)dynsmem;
    const int z = blockIdx.z;
    const size_t offAB = (size_t)(z >> 4) * zb + (size_t)(z & 15) * zh;

    const int m0 = blockIdx.y * 128, n0 = blockIdx.x * 128;
    const int tid = threadIdx.x, lane = tid & 31, wid = tid >> 5;
    const int wm0 = (wid >> 2) * 64, wn0 = (wid & 3) * 32;
    const int lr = lane >> 2, lc = lane & 3;

    const int rowA = lane & 15;
    const int kA = (lane >> 4) * 8;
    const int rowB = (lane & 7) + ((lane >> 4) * 8);
    const int kB = ((lane >> 3) & 1) * 8;

    const uint32_t sbase = s2u(smem);

    float acc[4][4][4];
#pragma unroll
    for (int i = 0; i < 4; i++)
#pragma unroll
        for (int j = 0; j < 4; j++)
#pragma unroll
            for (int k = 0; k < 4; k++) acc[i][j][k] = 0.0f;

    const int nk = K / 32;

    auto loadAB = [&](int buf, int k0) {
#pragma unroll
        for (int j = 0; j < 2; j++) {
            int idx = tid + j * 256;
            int r = idx >> 2, cc = idx & 3;
            int rp = r * PITCH + cc * 8;
            size_t gA = offAB + (size_t)(m0 + r) * lda + k0 + cc * 8;
            size_t gB = offAB + (size_t)(n0 + r) * ldb + k0 + cc * 8;
            cpa16(sbase + (slot_off(0, buf) + rp) * 2, Ah + gA);
            cpa16(sbase + (slot_off(1, buf) + rp) * 2, Al + gA);
            cpa16(sbase + (slot_off(2, buf) + rp) * 2, Bth + gB);
            cpa16(sbase + (slot_off(3, buf) + rp) * 2, Btl + gB);
        }
    };

    loadAB(0, 0);
    cp_commit();

    for (int kt = 0; kt < nk; kt++) {
        const int buf = kt & 1;
        if (kt + 1 < nk) {
            loadAB(buf ^ 1, (kt + 1) * 32);
            cp_commit();
            cp_wait1();
        } else {
            cp_wait0();
        }
        __syncthreads();

#pragma unroll
        for (int ks = 0; ks < 32; ks += 16) {
            uint32_t ah[4][4], al[4][4];
#pragma unroll
            for (int mt = 0; mt < 4; mt++) {
                uint32_t aoff = ((wm0 + mt * 16 + rowA) * PITCH + ks + kA) * 2;
                ldsm4(sbase + slot_off(0, buf) * 2 + aoff,
                      ah[mt][0], ah[mt][1], ah[mt][2], ah[mt][3]);
                ldsm4(sbase + slot_off(1, buf) * 2 + aoff,
                      al[mt][0], al[mt][1], al[mt][2], al[mt][3]);
            }
            uint32_t bhq[2][4], blq[2][4];
#pragma unroll
            for (int np = 0; np < 2; np++) {
                uint32_t boff = ((wn0 + np * 16 + rowB) * PITCH + ks + kB) * 2;
                ldsm4(sbase + slot_off(2, buf) * 2 + boff,
                      bhq[np][0], bhq[np][1], bhq[np][2], bhq[np][3]);
                ldsm4(sbase + slot_off(3, buf) * 2 + boff,
                      blq[np][0], blq[np][1], blq[np][2], blq[np][3]);
            }
#pragma unroll
            for (int nt = 0; nt < 4; nt++) {
                uint32_t bh[2] = {bhq[nt >> 1][(nt & 1) * 2],
                                  bhq[nt >> 1][(nt & 1) * 2 + 1]};
                uint32_t bl[2] = {blq[nt >> 1][(nt & 1) * 2],
                                  blq[nt >> 1][(nt & 1) * 2 + 1]};
#pragma unroll
                for (int mt = 0; mt < 4; mt++) {
                    mma16(acc[mt][nt], ah[mt], bh);
                    mma16(acc[mt][nt], ah[mt], bl);
                    mma16(acc[mt][nt], al[mt], bh);
                }
            }
        }
        __syncthreads();
    }

    // epilogue
#pragma unroll
    for (int mt = 0; mt < 4; mt++)
#pragma unroll
        for (int nt = 0; nt < 4; nt++) {
            int r = m0 + wm0 + mt * 16 + lr;
            int c = n0 + wn0 + nt * 8 + 2 * lc;
            float b0 = 0.0f, b1 = 0.0f;
            if (bias) {
                const float* bp = (c >= nsplit) ? (biasB - nsplit) : bias;
                b0 = bp[c]; b1 = bp[c + 1];
            }
            float v00 = acc[mt][nt][0] * scale + b0;
            float v01 = acc[mt][nt][1] * scale + b1;
            float v10 = acc[mt][nt][2] * scale + b0;
            float v11 = acc[mt][nt][3] * scale + b1;
            if (OUT == 0) {
                float* C = outF + (size_t)z * cB;
                *(float2*)(C + (size_t)r * ldc + c) = make_float2(v00, v01);
                *(float2*)(C + (size_t)(r + 8) * ldc + c) = make_float2(v10, v11);
            } else if (OUT == 1) {
                bf16 h0, l0, h1, l1;
                split_bf(v00, h0, l0); split_bf(v01, h1, l1);
                *(uint32_t*)(outH + (size_t)r * ldc + c) = pk2(h0, h1);
                *(uint32_t*)(outL + (size_t)r * ldc + c) = pk2(l0, l1);
                split_bf(v10, h0, l0); split_bf(v11, h1, l1);
                *(uint32_t*)(outH + (size_t)(r + 8) * ldc + c) = pk2(h0, h1);
                *(uint32_t*)(outL + (size_t)(r + 8) * ldc + c) = pk2(l0, l1);
            } else {
                bf16 h, l;
                split_bf(v00, h, l);
                outH[(size_t)c * ldc + r] = h; outL[(size_t)c * ldc + r] = l;
                split_bf(v01, h, l);
                outH[(size_t)(c + 1) * ldc + r] = h; outL[(size_t)(c + 1) * ldc + r] = l;
                split_bf(v10, h, l);
                outH[(size_t)c * ldc + r + 8] = h; outL[(size_t)c * ldc + r + 8] = l;
                split_bf(v11, h, l);
                outH[(size_t)(c + 1) * ldc + r + 8] = h; outL[(size_t)(c + 1) * ldc + r + 8] = l;
            }
        }
}

// ---------------- softmax: probs -> attn (d_out), float4 I/O -----------------
#define SMROW 1032
#define SOFT_SMEM (16 * SMROW * 4)
__global__ __launch_bounds__(256) void softmax_kernel(
    const float* __restrict__ Sc, float* __restrict__ attn)
{
    float* ssc = (float*)dynsmem;
    __shared__ float mF[16], iF[16], mB[16], iB[16];

    const int bh = blockIdx.y;
    const int q0 = blockIdx.x * 16;
    const int tid = threadIdx.x;

    const float4* src4 = (const float4*)(Sc + (size_t)bh * SS * SS + (size_t)q0 * SS);
    for (int i = tid; i < 16 * 256; i += 256) {
        int r = i >> 8, c = i & 255;
        *(float4*)(ssc + r * SMROW + c * 4) = src4[r * 256 + c];
    }
    __syncthreads();

    const int r = tid >> 4;
    const int t = tid & 15;
    const int q = q0 + r;
    const float* row = ssc + r * SMROW;

    float mf = -1e30f, mb = -1e30f;
#pragma unroll 8
    for (int i = 0; i < 64; i++) {
        int k = t + (i << 4);
        float v = row[k];
        if (k <= q) mf = fmaxf(mf, v);
        if (k >= q) mb = fmaxf(mb, v);
    }
#pragma unroll
    for (int o = 8; o > 0; o >>= 1) {
        mf = fmaxf(mf, __shfl_xor_sync(0xffffffffu, mf, o));
        mb = fmaxf(mb, __shfl_xor_sync(0xffffffffu, mb, o));
    }
    float sf = 0.0f, sb2 = 0.0f;
#pragma unroll 8
    for (int i = 0; i < 64; i++) {
        int k = t + (i << 4);
        float v = row[k];
        if (k <= q) sf += __expf(v - mf);
        if (k >= q) sb2 += __expf(v - mb);
    }
#pragma unroll
    for (int o = 8; o > 0; o >>= 1) {
        sf += __shfl_xor_sync(0xffffffffu, sf, o);
        sb2 += __shfl_xor_sync(0xffffffffu, sb2, o);
    }
    if (t == 0) {
        mF[r] = mf; iF[r] = 1.0f / sf;
        mB[r] = mb; iB[r] = 1.0f / sb2;
    }
    __syncthreads();

    float* dst = attn + (size_t)bh * SS * 2 * SS + (size_t)q0 * 2048;
    for (int i = tid; i < 16 * 256; i += 256) {
        int rr = i >> 8, c = (i & 255) * 4;
        int qq = q0 + rr;
        float4 v = *(const float4*)(ssc + rr * SMROW + c);
        float mf2 = mF[rr], if2 = iF[rr], mb2 = mB[rr], ib2 = iB[rr];
        float4 pf, pb;
        pf.x = (c + 0 <= qq) ? __expf(v.x - mf2) * if2 : 0.0f;
        pf.y = (c + 1 <= qq) ? __expf(v.y - mf2) * if2 : 0.0f;
        pf.z = (c + 2 <= qq) ? __expf(v.z - mf2) * if2 : 0.0f;
        pf.w = (c + 3 <= qq) ? __expf(v.w - mf2) * if2 : 0.0f;
        pb.x = (c + 0 >= qq) ? __expf(v.x - mb2) * ib2 : 0.0f;
        pb.y = (c + 1 >= qq) ? __expf(v.y - mb2) * ib2 : 0.0f;
        pb.z = (c + 2 >= qq) ? __expf(v.z - mb2) * ib2 : 0.0f;
        pb.w = (c + 3 >= qq) ? __expf(v.w - mb2) * ib2 : 0.0f;
        *(float4*)(dst + (size_t)rr * 2048 + c) = pf;
        *(float4*)(dst + (size_t)rr * 2048 + 1024 + c) = pb;
    }
}

// ---------------- PV: ctx = P @ V  (ldmatrix + cp.async) --------------------
#define VSZ (32 * PITCH)
#define PV_SMEM ((4 * TSZ + 4 * VSZ) * 2)   // 51200 B

__global__ __launch_bounds__(256, 2) void pv_bf16(const float* __restrict__ attn)
{
    bf16* smem = (bf16*)dynsmem;

    const int bh = blockIdx.z;
    const int dir = blockIdx.y;
    const int q0 = blockIdx.x * 128;
    const int b = bh >> 4, h = bh & 15;
    const int tid = threadIdx.x, lane = tid & 31, wid = tid >> 5;
    const int lr = lane >> 2, lc = lane & 3;

    const int rowA = lane & 15;
    const int kA = (lane >> 4) * 8;
    const int rowB = (lane & 7) + ((lane >> 4) * 8);
    const int kB = ((lane >> 3) & 1) * 8;

    const float* Pb = attn + (size_t)bh * SS * 2 * SS + (size_t)dir * SS;
    const bf16* Vth = g_VTh + (size_t)h * 32 * BS + (size_t)b * SS;
    const bf16* Vtl = g_VTl + (size_t)h * 32 * BS + (size_t)b * SS;

    const uint32_t sbase = s2u(smem);

    float acc[4][4];
#pragma unroll
    for (int i = 0; i < 4; i++)
#pragma unroll
        for (int j = 0; j < 4; j++) acc[i][j] = 0.0f;

    auto loadP = [&](int buf, int k0) {
#pragma unroll
        for (int j = 0; j < 2; j++) {
            int idx = tid + j * 256;
            int r = idx >> 2, cc = idx & 3;
            const float* src = Pb + (size_t)(q0 + r) * 2048 + k0 + cc * 8;
            float4 p0 = *(const float4*)(src);
            float4 p1 = *(const float4*)(src + 4);
            bf16 h0, l0, h1, l1, h2, l2, h3, l3, h4, l4, h5, l5, h6, l6, h7, l7;
            split_bf(p0.x, h0, l0); split_bf(p0.y, h1, l1);
            split_bf(p0.z, h2, l2); split_bf(p0.w, h3, l3);
            split_bf(p1.x, h4, l4); split_bf(p1.y, h5, l5);
            split_bf(p1.z, h6, l6); split_bf(p1.w, h7, l7);
            uint4 hv = make_uint4(pk2(h0, h1), pk2(h2, h3), pk2(h4, h5), pk2(h6, h7));
            uint4 lv = make_uint4(pk2(l0, l1), pk2(l2, l3), pk2(l4, l5), pk2(l6, l7));
            *(uint4*)(smem + (0 * 2 + buf) * TSZ + r * PITCH + cc * 8) = hv;
            *(uint4*)(smem + (1 * 2 + buf) * TSZ + r * PITCH + cc * 8) = lv;
        }
    };
    auto loadV = [&](int buf, int k0) {
        int half = tid >> 7;
        int d = (tid >> 2) & 31;
        int cc = tid & 3;
        const bf16* src = (half == 0 ? Vth : Vtl);
        uint32_t s = sbase + (4 * TSZ + (half * 2 + buf) * VSZ
                              + d * PITCH + cc * 8) * 2;
        cpa16(s, src + (size_t)d * BS + k0 + cc * 8);
    };

    loadV(0, 0);
    cp_commit();
    loadP(0, 0);

    const int nk = SS / 32;
    for (int kt = 0; kt < nk; kt++) {
        const int buf = kt & 1;
        if (kt + 1 < nk) {
            loadV(buf ^ 1, (kt + 1) * 32);
            cp_commit();
            cp_wait1();
        } else {
            cp_wait0();
        }
        __syncthreads();
        if (kt + 1 < nk) loadP(buf ^ 1, (kt + 1) * 32);

#pragma unroll
        for (int ks = 0; ks < 32; ks += 16) {
            uint32_t aoff = ((wid * 16 + rowA) * PITCH + ks + kA) * 2;
            uint32_t ah[4], al[4];
            ldsm4(sbase + ((0 * 2 + buf) * TSZ) * 2 + aoff, ah[0], ah[1], ah[2], ah[3]);
            ldsm4(sbase + ((1 * 2 + buf) * TSZ) * 2 + aoff, al[0], al[1], al[2], al[3]);
            uint32_t bhq[2][4], blq[2][4];
#pragma unroll
            for (int np = 0; np < 2; np++) {
                uint32_t boff = ((np * 16 + rowB) * PITCH + ks + kB) * 2;
                ldsm4(sbase + (4 * TSZ + (0 * 2 + buf) * VSZ) * 2 + boff,
                      bhq[np][0], bhq[np][1], bhq[np][2], bhq[np][3]);
                ldsm4(sbase + (4 * TSZ + (1 * 2 + buf) * VSZ) * 2 + boff,
                      blq[np][0], blq[np][1], blq[np][2], blq[np][3]);
            }
#pragma unroll
            for (int nt = 0; nt < 4; nt++) {
                uint32_t bh[2] = {bhq[nt >> 1][(nt & 1) * 2],
                                  bhq[nt >> 1][(nt & 1) * 2 + 1]};
                uint32_t bl[2] = {blq[nt >> 1][(nt & 1) * 2],
                                  blq[nt >> 1][(nt & 1) * 2 + 1]};
                mma16(acc[nt], ah, bh);
                mma16(acc[nt], ah, bl);
                mma16(acc[nt], al, bh);
            }
        }
        __syncthreads();
    }

#pragma unroll
    for (int nt = 0; nt < 4; nt++) {
        int r = q0 + wid * 16 + lr;
        int c = dir * HDV + h * DV + nt * 8 + 2 * lc;
        bf16 h0, l0, h1, l1;
        split_bf(acc[nt][0], h0, l0); split_bf(acc[nt][1], h1, l1);
        *(uint32_t*)(g_Ch + (size_t)((size_t)b * SS + r) * DD + c) = pk2(h0, h1);
        *(uint32_t*)(g_Cl + (size_t)((size_t)b * SS + r) * DD + c) = pk2(l0, l1);
        split_bf(acc[nt][2], h0, l0); split_bf(acc[nt][3], h1, l1);
        *(uint32_t*)(g_Ch + (size_t)((size_t)b * SS + r + 8) * DD + c) = pk2(h0, h1);
        *(uint32_t*)(g_Cl + (size_t)((size_t)b * SS + r + 8) * DD + c) = pk2(l0, l1);
    }
}

// ---------------- launch -----------------------------------------------------
extern "C" void kernel_launch(void* const* d_in, const int* in_sizes, int n_in,
                              void* d_out, int out_size)
{
    const float* x  = (const float*)d_in[0];
    const float* Wq = (const float*)d_in[1];
    const float* bq = (const float*)d_in[2];
    const float* Wk = (const float*)d_in[3];
    const float* bk = (const float*)d_in[4];
    const float* Wv = (const float*)d_in[5];
    const float* bv = (const float*)d_in[6];
    const float* Wo = (const float*)d_in[7];
    const float* bo = (const float*)d_in[8];

    float* out  = (float*)d_out;
    float* attn = out + (size_t)BS * DD;

    bf16 *xh, *xl, *WqkTh, *WqkTl, *WvTh, *WvTl, *WoTh, *WoTl;
    bf16 *QKh, *QKl, *VTh, *VTl, *Ch, *Cl;
    float* pS;
    cudaGetSymbolAddress((void**)&xh, g_xh);       cudaGetSymbolAddress((void**)&xl, g_xl);
    cudaGetSymbolAddress((void**)&WqkTh, g_WqkTh); cudaGetSymbolAddress((void**)&WqkTl, g_WqkTl);
    cudaGetSymbolAddress((void**)&WvTh, g_WvTh);   cudaGetSymbolAddress((void**)&WvTl, g_WvTl);
    cudaGetSymbolAddress((void**)&WoTh, g_WoTh);   cudaGetSymbolAddress((void**)&WoTl, g_WoTl);
    cudaGetSymbolAddress((void**)&QKh, g_QKh);     cudaGetSymbolAddress((void**)&QKl, g_QKl);
    cudaGetSymbolAddress((void**)&VTh, g_VTh);     cudaGetSymbolAddress((void**)&VTl, g_VTl);
    cudaGetSymbolAddress((void**)&Ch, g_Ch);       cudaGetSymbolAddress((void**)&Cl, g_Cl);
    cudaGetSymbolAddress((void**)&pS, g_S);

    cudaFuncSetAttribute(gemm_bf16<0>, cudaFuncAttributeMaxDynamicSharedMemorySize, GEMM_SMEM);
    cudaFuncSetAttribute(gemm_bf16<1>, cudaFuncAttributeMaxDynamicSharedMemorySize, GEMM_SMEM);
    cudaFuncSetAttribute(gemm_bf16<2>, cudaFuncAttributeMaxDynamicSharedMemorySize, GEMM_SMEM);
    cudaFuncSetAttribute(pv_bf16, cudaFuncAttributeMaxDynamicSharedMemorySize, PV_SMEM);
    cudaFuncSetAttribute(softmax_kernel,
                         cudaFuncAttributeMaxDynamicSharedMemorySize, SOFT_SMEM);

    // split passes (2 launches)
    split_x_kernel<<<512, 256>>>(x, xh, xl, BS * DD / 4);
    SplitArgs sa;
    sa.W[0] = Wq; sa.Th[0] = WqkTh;                    sa.Tl[0] = WqkTl;                    sa.N[0] = HDQ;
    sa.W[1] = Wk; sa.Th[1] = WqkTh + (size_t)HDQ * DD; sa.Tl[1] = WqkTl + (size_t)HDQ * DD; sa.N[1] = HDQ;
    sa.W[2] = Wv; sa.Th[2] = WvTh;                     sa.Tl[2] = WvTl;                     sa.N[2] = HDV;
    sa.W[3] = Wo; sa.Th[3] = WoTh;                     sa.Tl[3] = WoTl;                     sa.N[3] = DD;
    splitT_all<<<dim3(32, 32, 4), dim3(32, 8)>>>(sa);

    // merged QK projection: one launch, N=2048, bias bq for c<1024, bk after
    gemm_bf16<1><<<dim3(16, 32, 1), 256, GEMM_SMEM>>>(
        xh, xl, DD, WqkTh, WqkTl, DD, bq, bk, HDQ, 1.0f,
        nullptr, QKh, QKl, 2 * HDQ, BS, 2 * HDQ, DD, 0, 0, 0);
    gemm_bf16<2><<<dim3(4, 32, 1), 256, GEMM_SMEM>>>(
        xh, xl, DD, WvTh, WvTl, DD, bv, bv, HDV, 1.0f,
        nullptr, VTh, VTl, BS, BS, HDV, DD, 0, 0, 0);

    // scores: per (b,h) Q @ K^T * 0.125 (Q at col 0, K at col 1024 of QK)
    gemm_bf16<0><<<dim3(8, 8, BB * HH), 256, GEMM_SMEM>>>(
        QKh, QKl, 2 * HDQ, QKh + HDQ, QKl + HDQ, 2 * HDQ, nullptr, nullptr, SS, 0.125f,
        pS, nullptr, nullptr, SS, SS, SS, DQ,
        (size_t)SS * 2 * HDQ, (size_t)DQ, (size_t)SS * SS);

    // softmax + prob write (float4 I/O)
    softmax_kernel<<<dim3(SS / 16, BB * HH), 256, SOFT_SMEM>>>(pS, attn);

    // PV
    pv_bf16<<<dim3(SS / 128, 2, BB * HH), 256, PV_SMEM>>>(attn);

    // output projection
    gemm_bf16<0><<<dim3(8, 32, 1), 256, GEMM_SMEM>>>(
        Ch, Cl, DD, WoTh, WoTl, DD, bo, bo, DD, 1.0f,
        out, nullptr, nullptr, DD, BS, DD, DD, 0, 0, 0);
}